// round 12
// baseline (speedup 1.0000x reference)
#include <cuda_runtime.h>
#include <cuda_bf16.h>
#include <cstdint>

// ---------------------------------------------------------------------------
// Problem dims
// ---------------------------------------------------------------------------
#define BATCH   4096
#define IN_DIM  1024
#define OUT_DIM 1024
#define KBIG    4096          // 4 * IN_DIM

// GEMM tiling: BM=256, BN=128, 256 threads, warp grid 4x2, warp tile 64x64.
// Fused-3-segment (Ah*Wh + Al*Wh + Ah*Wl into one accumulator).
// BK=32, 4 stages, ONE barrier per chunk, loads issued before compute.
// K-split: mains do chunks [0,112), 24 helpers do [112,128) x 5-6 tiles each.
#define BM 256
#define BN 128
#define BK 32                 // bf16 -> 64 bytes per row
#define NCHUNK (KBIG / BK)    // 128
#define CK_MAIN 112           // chunks done by main CTAs (balanced vs helpers)
#define NTILES  128           // (4096/256) * (1024/128)
#define NHELP   24
#define NBLOCKS (NTILES + NHELP)   // 152
#define STAGES 4
#define NTHREADS 256
#define TILE_AH  0                        // 16 KB (256 rows x 64 B)
#define TILE_AL  (BM * 64)                // 16 KB
#define TILE_WH  (2 * BM * 64)            // 8 KB (128 rows x 64 B)
#define TILE_WL  (2 * BM * 64 + BN * 64)  // 8 KB
#define STAGE_BYTES  (2 * BM * 64 + 2 * BN * 64)     // 48 KB
#define SMEM_TOTAL   (STAGES * STAGE_BYTES)          // 192 KB

// SW64 swizzle for 64-byte rows (Swizzle<2,4,3>): bits[4:5] ^= bits[7:8]
#define SMEM_SWIZZLE_64B(off) ((off) ^ (((off) >> 3) & 0x30))

// ---------------------------------------------------------------------------
// Device scratch (allocation-free rule: __device__ globals)
// ---------------------------------------------------------------------------
__device__ float          g_coef[BATCH * 4];
__device__ __nv_bfloat16  g_Ah[BATCH * KBIG];         // 32 MB
__device__ __nv_bfloat16  g_Al[BATCH * KBIG];         // 32 MB
__device__ __nv_bfloat16  g_Wh[4 * OUT_DIM * IN_DIM]; // 8 MB
__device__ __nv_bfloat16  g_Wl[4 * OUT_DIM * IN_DIM]; // 8 MB
__device__ float          g_scratch[BATCH * OUT_DIM]; // 16 MB helper partials
__device__ int            g_flag[NTILES];

// ---------------------------------------------------------------------------
// PTX helpers (baseline ISA only)
// ---------------------------------------------------------------------------
__device__ __forceinline__ uint32_t smem_to_u32(const void* p) {
    uint32_t a;
    asm("{ .reg .u64 t; cvta.to.shared.u64 t, %1; cvt.u32.u64 %0, t; }"
        : "=r"(a) : "l"(p));
    return a;
}

__device__ __forceinline__ void cp_async16(uint32_t saddr, const void* gaddr) {
    asm volatile("cp.async.cg.shared.global [%0], [%1], 16;"
                 :: "r"(saddr), "l"(gaddr));
}

#define CP_ASYNC_COMMIT() asm volatile("cp.async.commit_group;" ::: "memory")
#define CP_ASYNC_WAIT2()  asm volatile("cp.async.wait_group 2;" ::: "memory")
#define CP_ASYNC_WAIT0()  asm volatile("cp.async.wait_group 0;" ::: "memory")

__device__ __forceinline__ void ldsm_x4(uint32_t (&r)[4], uint32_t addr) {
    asm volatile("ldmatrix.sync.aligned.m8n8.x4.shared.b16 {%0,%1,%2,%3}, [%4];"
                 : "=r"(r[0]), "=r"(r[1]), "=r"(r[2]), "=r"(r[3]) : "r"(addr));
}

__device__ __forceinline__ void mma_16816(float (&d)[4], const uint32_t (&a)[4],
                                          uint32_t b0, uint32_t b1) {
    asm volatile(
        "mma.sync.aligned.m16n8k16.row.col.f32.bf16.bf16.f32 "
        "{%0,%1,%2,%3}, {%4,%5,%6,%7}, {%8,%9}, {%0,%1,%2,%3};"
        : "+f"(d[0]), "+f"(d[1]), "+f"(d[2]), "+f"(d[3])
        : "r"(a[0]), "r"(a[1]), "r"(a[2]), "r"(a[3]), "r"(b0), "r"(b1));
}

// ---------------------------------------------------------------------------
// Split helpers
// ---------------------------------------------------------------------------
__device__ __forceinline__ uint32_t pack2bf16(__nv_bfloat16 lo, __nv_bfloat16 hi)
{
    return ((uint32_t)__bfloat16_as_ushort(hi) << 16) |
           (uint32_t)__bfloat16_as_ushort(lo);
}

__device__ __forceinline__ void split1(float a, __nv_bfloat16& h, __nv_bfloat16& l)
{
    h = __float2bfloat16(a);
    l = __float2bfloat16(a - __bfloat162float(h));
}

// ---------------------------------------------------------------------------
// Kernel 1 (merged preprocessing):
//   blocks [0, BATCH):             coef + A = c*x split into bf16 hi/lo
//   blocks [BATCH, BATCH+1024):    weights -> bf16 hi/lo (1024*256*4 = 2^20 float4)
// ---------------------------------------------------------------------------
__global__ void __launch_bounds__(256)
prep_kernel(const float* __restrict__ x,
            const float* __restrict__ phase,
            const float* __restrict__ basis,
            const float* __restrict__ w)
{
    const int iv = threadIdx.x;

    if (blockIdx.x >= BATCH) {
        const int blk = blockIdx.x - BATCH;          // 0..1023
        if (blk == 0 && iv < NTILES) g_flag[iv] = 0; // per-launch flag clear
        size_t t0 = (size_t)blk * 1024 + iv;         // float4 index
#pragma unroll
        for (int r = 0; r < 4; r++) {
            size_t t = t0 + (size_t)r * 256;
            float4 wv = reinterpret_cast<const float4*>(w)[t];
            __nv_bfloat16 h0, h1, h2, h3, l0, l1, l2, l3;
            split1(wv.x, h0, l0); split1(wv.y, h1, l1);
            split1(wv.z, h2, l2); split1(wv.w, h3, l3);
            size_t base = t * 4;
            uint2 vh = make_uint2(pack2bf16(h0, h1), pack2bf16(h2, h3));
            uint2 vl = make_uint2(pack2bf16(l0, l1), pack2bf16(l2, l3));
            *reinterpret_cast<uint2*>(g_Wh + base) = vh;
            *reinterpret_cast<uint2*>(g_Wl + base) = vl;
        }
        return;
    }

    // ---- A split: one block per batch row ----
    const int b = blockIdx.x;
    const float HALF_PI = 1.5707963267948966f;
    float r = phase[b] / HALF_PI;
    int q = (int)floorf(r);
    q = min(max(q, 0), 3);
    float t  = r - (float)q;
    float t2 = t * t;
    float t3 = t2 * t;
    float co[4];
#pragma unroll
    for (int k = 0; k < 4; k++)
        co[k] = t3 * basis[k] + t2 * basis[4 + k] + t * basis[8 + k] + basis[12 + k];
    float cs[4];
#pragma unroll
    for (int j = 0; j < 4; j++) cs[j] = co[(j - q + 1) & 3];
    if (iv < 4) g_coef[b * 4 + iv] = cs[iv];

    float4 xv = reinterpret_cast<const float4*>(x)[b * 256 + iv];
#pragma unroll
    for (int j = 0; j < 4; j++) {
        float a0 = cs[j] * xv.x, a1 = cs[j] * xv.y;
        float a2 = cs[j] * xv.z, a3 = cs[j] * xv.w;
        __nv_bfloat16 h0, h1, h2, h3, l0, l1, l2, l3;
        split1(a0, h0, l0); split1(a1, h1, l1);
        split1(a2, h2, l2); split1(a3, h3, l3);
        size_t base = (size_t)b * KBIG + j * IN_DIM + iv * 4;
        uint2 vh = make_uint2(pack2bf16(h0, h1), pack2bf16(h2, h3));
        uint2 vl = make_uint2(pack2bf16(l0, l1), pack2bf16(l2, l3));
        *reinterpret_cast<uint2*>(g_Ah + base) = vh;
        *reinterpret_cast<uint2*>(g_Al + base) = vl;
    }
}

// ---------------------------------------------------------------------------
// Kernel 2: fused-3-segment mma.sync bf16 GEMM with K-split helpers
// ---------------------------------------------------------------------------
__device__ __forceinline__ void issue_tile_load(
    uint32_t smem_base, int stage, int ck, int tid, int mBase, int nBase)
{
    const int kA = ck * BK;
    const int j  = kA >> 10;
    const int i0 = kA & (IN_DIM - 1);
    const size_t wOff = (size_t)j * (OUT_DIM * IN_DIM) + i0;

    const uint32_t st = smem_base + stage * STAGE_BYTES;

    // A: 256 rows x 4 vec16 = 1024 vectors -> 4 per thread (x2 arrays)
#pragma unroll
    for (int it = 0; it < 4; it++) {
        int idx = tid + it * NTHREADS;
        int row = idx >> 2;
        int cv  = idx & 3;
        size_t goff = (size_t)(mBase + row) * KBIG + kA + cv * 8;
        uint32_t soff = SMEM_SWIZZLE_64B(row * 64 + cv * 16);
        cp_async16(st + TILE_AH + soff, g_Ah + goff);
        cp_async16(st + TILE_AL + soff, g_Al + goff);
    }
    // W: 128 rows x 4 vec16 = 512 vectors -> 2 per thread (x2 arrays)
#pragma unroll
    for (int it = 0; it < 2; it++) {
        int idx = tid + it * NTHREADS;
        int row = idx >> 2;
        int cv  = idx & 3;
        size_t goff = wOff + (size_t)(nBase + row) * IN_DIM + cv * 8;
        uint32_t soff = SMEM_SWIZZLE_64B(row * 64 + cv * 16);
        cp_async16(st + TILE_WH + soff, g_Wh + goff);
        cp_async16(st + TILE_WL + soff, g_Wl + goff);
    }
}

// Run nck chunks [ck0, ck0+nck).
// Per iteration: wait(2) -> ONE sync -> issue chunk i+3 (stage free by
// construction) -> compute 2 k16 steps. Unconditional commit keeps the
// one-group-per-iteration accounting exact.
__device__ __forceinline__ void run_chunks(
    uint32_t smem_base, int tid, int lane, int wm, int wn,
    int mBase, int nBase, int ck0, int nck, float (&acc)[4][8][4])
{
    const int a_row  = lane & 15;
    const int a_colh = (lane >> 4) * 16;
    const int b_row  = (lane & 7) + ((lane >> 4) << 3);
    const int b_colh = ((lane >> 3) & 1) * 16;

    const int aBase = (wm * 64 + a_row) * 64 + a_colh;   // + mt*1024 + kc
    const int bBase = (wn * 64 + b_row) * 64 + b_colh;   // + nt2*1024 + kc

    // Prologue: 3 chunks in flight
#pragma unroll
    for (int p = 0; p < 3; p++) {
        if (p < nck) issue_tile_load(smem_base, p & 3, ck0 + p, tid, mBase, nBase);
        CP_ASYNC_COMMIT();
    }

#pragma unroll 1
    for (int i = 0; i < nck; i++) {
        CP_ASYNC_WAIT2();          // chunk i's group complete
        __syncthreads();           // all warps done with stage (i-1)&3

        {
            int lck = i + 3;
            if (lck < nck)
                issue_tile_load(smem_base, lck & 3, ck0 + lck, tid, mBase, nBase);
            CP_ASYNC_COMMIT();
        }

        const uint32_t st = smem_base + (i & 3) * STAGE_BYTES;
        const uint32_t sah = st + TILE_AH;
        const uint32_t sal = st + TILE_AL;
        const uint32_t swh = st + TILE_WH;
        const uint32_t swl = st + TILE_WL;

#pragma unroll
        for (int ks = 0; ks < 2; ks++) {       // 2 x k16 within BK=32
            const int kc = ks * 32;
            uint32_t aF[4][4];     // aH, later reused for aL
            uint32_t bH[8][2];
            uint32_t bX[8][2];     // bL

            // ---- step 1: aH, bH -> aH*bH ----
#pragma unroll
            for (int mt = 0; mt < 4; mt++)
                ldsm_x4(aF[mt], sah + SMEM_SWIZZLE_64B(aBase + mt * 1024 + kc));
#pragma unroll
            for (int nt2 = 0; nt2 < 4; nt2++) {
                uint32_t b4[4];
                ldsm_x4(b4, swh + SMEM_SWIZZLE_64B(bBase + nt2 * 1024 + kc));
                bH[nt2 * 2 + 0][0] = b4[0]; bH[nt2 * 2 + 0][1] = b4[1];
                bH[nt2 * 2 + 1][0] = b4[2]; bH[nt2 * 2 + 1][1] = b4[3];
            }
#pragma unroll
            for (int mt = 0; mt < 4; mt++)
#pragma unroll
                for (int nt = 0; nt < 8; nt++)
                    mma_16816(acc[mt][nt], aF[mt], bH[nt][0], bH[nt][1]);

            // ---- step 2: bL -> aH*bL ----
#pragma unroll
            for (int nt2 = 0; nt2 < 4; nt2++) {
                uint32_t b4[4];
                ldsm_x4(b4, swl + SMEM_SWIZZLE_64B(bBase + nt2 * 1024 + kc));
                bX[nt2 * 2 + 0][0] = b4[0]; bX[nt2 * 2 + 0][1] = b4[1];
                bX[nt2 * 2 + 1][0] = b4[2]; bX[nt2 * 2 + 1][1] = b4[3];
            }
#pragma unroll
            for (int mt = 0; mt < 4; mt++)
#pragma unroll
                for (int nt = 0; nt < 8; nt++)
                    mma_16816(acc[mt][nt], aF[mt], bX[nt][0], bX[nt][1]);

            // ---- step 3: aL (reuses aF) -> aL*bH ----
#pragma unroll
            for (int mt = 0; mt < 4; mt++)
                ldsm_x4(aF[mt], sal + SMEM_SWIZZLE_64B(aBase + mt * 1024 + kc));
#pragma unroll
            for (int mt = 0; mt < 4; mt++)
#pragma unroll
                for (int nt = 0; nt < 8; nt++)
                    mma_16816(acc[mt][nt], aF[mt], bH[nt][0], bH[nt][1]);
        }
    }
    CP_ASYNC_WAIT0();
}

__global__ void __launch_bounds__(NTHREADS, 1)
gemm_kernel(const float* __restrict__ biases, float* __restrict__ out)
{
    extern __shared__ char smem[];
    const uint32_t smem_base = smem_to_u32(smem);
    const int tid  = threadIdx.x;
    const int wid  = tid >> 5;
    const int lane = tid & 31;
    const int wm   = wid & 3;    // 4 warp rows (64 rows each)
    const int wn   = wid >> 2;   // 2 warp cols (64 cols each)
    const int tg   = lane >> 2;
    const int tc   = (lane & 3) * 2;

    if (blockIdx.x < NHELP) {
        // ------------------- HELPER CTA: chunks [CK_MAIN, 128) -------------------
        const int h = blockIdx.x;
#pragma unroll 1
        for (int t = h; t < NTILES; t += NHELP) {
            const int mBase = (t & 15) * BM;
            const int nBase = (t >> 4) * BN;

            float acc[4][8][4];
#pragma unroll
            for (int i = 0; i < 4; i++)
#pragma unroll
                for (int j = 0; j < 8; j++)
#pragma unroll
                    for (int k = 0; k < 4; k++) acc[i][j][k] = 0.f;

            run_chunks(smem_base, tid, lane, wm, wn, mBase, nBase,
                       CK_MAIN, NCHUNK - CK_MAIN, acc);

#pragma unroll
            for (int nt = 0; nt < 8; nt++) {
                int col = nBase + wn * 64 + nt * 8 + tc;
#pragma unroll
                for (int mt = 0; mt < 4; mt++) {
                    int r0 = mBase + wm * 64 + mt * 16 + tg;
                    float2 r01 = make_float2(acc[mt][nt][0], acc[mt][nt][1]);
                    float2 r23 = make_float2(acc[mt][nt][2], acc[mt][nt][3]);
                    *reinterpret_cast<float2*>(g_scratch + (size_t)r0 * OUT_DIM + col) = r01;
                    *reinterpret_cast<float2*>(g_scratch + (size_t)(r0 + 8) * OUT_DIM + col) = r23;
                }
            }
            __threadfence();
            __syncthreads();
            if (tid == 0) {
                asm volatile("st.release.gpu.global.b32 [%0], %1;"
                             :: "l"(&g_flag[t]), "r"(1) : "memory");
            }
            __syncthreads();
        }
        return;
    }

    // --------------------- MAIN CTA: chunks [0, CK_MAIN) ---------------------
    const int t = blockIdx.x - NHELP;
    const int mBase = (t & 15) * BM;
    const int nBase = (t >> 4) * BN;

    float acc[4][8][4];
#pragma unroll
    for (int i = 0; i < 4; i++)
#pragma unroll
        for (int j = 0; j < 8; j++)
#pragma unroll
            for (int k = 0; k < 4; k++) acc[i][j][k] = 0.f;

    run_chunks(smem_base, tid, lane, wm, wn, mBase, nBase, 0, CK_MAIN, acc);

    // Wait for helper partial (helpers finish earlier by construction)
    if (tid == 0) {
        int f;
        do {
            asm volatile("ld.acquire.gpu.global.b32 %0, [%1];"
                         : "=r"(f) : "l"(&g_flag[t]) : "memory");
            if (!f) __nanosleep(64);
        } while (!f);
    }
    __syncthreads();

    // ---- Epilogue: D += scratch + sum_j c_j[b] * bias_j[o] ----
    float cA[4][4], cB[4][4];
#pragma unroll
    for (int mt = 0; mt < 4; mt++) {
        int r0 = mBase + wm * 64 + mt * 16 + tg;
#pragma unroll
        for (int j = 0; j < 4; j++) {
            cA[mt][j] = g_coef[r0 * 4 + j];
            cB[mt][j] = g_coef[(r0 + 8) * 4 + j];
        }
    }

#pragma unroll
    for (int nt = 0; nt < 8; nt++) {
        int col = nBase + wn * 64 + nt * 8 + tc;
        float2 bj[4];
#pragma unroll
        for (int j = 0; j < 4; j++)
            bj[j] = *reinterpret_cast<const float2*>(biases + j * OUT_DIM + col);
#pragma unroll
        for (int mt = 0; mt < 4; mt++) {
            int r0 = mBase + wm * 64 + mt * 16 + tg;
            float2 s01 = *reinterpret_cast<const float2*>(g_scratch + (size_t)r0 * OUT_DIM + col);
            float2 s23 = *reinterpret_cast<const float2*>(g_scratch + (size_t)(r0 + 8) * OUT_DIM + col);
            float be0 = 0.f, be1 = 0.f, be2 = 0.f, be3 = 0.f;
#pragma unroll
            for (int j = 0; j < 4; j++) {
                be0 += cA[mt][j] * bj[j].x;
                be1 += cA[mt][j] * bj[j].y;
                be2 += cB[mt][j] * bj[j].x;
                be3 += cB[mt][j] * bj[j].y;
            }
            float2 r01 = make_float2(acc[mt][nt][0] + be0 + s01.x,
                                     acc[mt][nt][1] + be1 + s01.y);
            float2 r23 = make_float2(acc[mt][nt][2] + be2 + s23.x,
                                     acc[mt][nt][3] + be3 + s23.y);
            *reinterpret_cast<float2*>(out + (size_t)r0 * OUT_DIM + col) = r01;
            *reinterpret_cast<float2*>(out + (size_t)(r0 + 8) * OUT_DIM + col) = r23;
        }
    }
}

// ---------------------------------------------------------------------------
// kernel_launch
// ---------------------------------------------------------------------------
extern "C" void kernel_launch(void* const* d_in, const int* in_sizes, int n_in,
                              void* d_out, int out_size)
{
    const float* x      = (const float*)d_in[0];
    const float* phase  = (const float*)d_in[1];
    const float* w      = (const float*)d_in[2];
    const float* biases = (const float*)d_in[3];
    const float* basis  = (const float*)d_in[4];
    float* out = (float*)d_out;

    static bool attr_set = false;
    if (!attr_set) {
        cudaFuncSetAttribute(gemm_kernel,
                             cudaFuncAttributeMaxDynamicSharedMemorySize,
                             SMEM_TOTAL);
        attr_set = true;
    }

    prep_kernel<<<BATCH + 1024, 256>>>(x, phase, basis, w);
    gemm_kernel<<<NBLOCKS, NTHREADS, SMEM_TOTAL>>>(biases, out);
}

// round 13
// speedup vs baseline: 1.0184x; 1.0184x over previous
#include <cuda_runtime.h>
#include <cuda_bf16.h>
#include <cstdint>

// ---------------------------------------------------------------------------
// Problem dims
// ---------------------------------------------------------------------------
#define BATCH   4096
#define IN_DIM  1024
#define OUT_DIM 1024
#define KBIG    4096          // 4 * IN_DIM

// GEMM: BM=128, BN=128, BK=32, 256 threads, warp grid 2x4, warp tile 64x32.
// 2 CTAs per SM (64KB smem, <=128 regs) so barrier/load stalls of one CTA are
// hidden by the co-resident CTA's MMA stream.
// Fused-3-segment (Ah*Wh + Al*Wh + Ah*Wl into one accumulator).
// K-split: 256 main CTAs do chunks [0,112), 48 helpers do [112,128).
#define BM 128
#define BN 128
#define BK 32                 // bf16 -> 64 bytes per row
#define NCHUNK (KBIG / BK)    // 128
#define CK_MAIN 112
#define NTILES  256           // (4096/128) * (1024/128)
#define NHELP   48
#define NBLOCKS (NTILES + NHELP)   // 304 = 2 * 152
#define STAGES 2
#define NTHREADS 256
#define TILE_AH  0                        // 8 KB (128 rows x 64 B)
#define TILE_AL  (BM * 64)                // 8 KB
#define TILE_WH  (2 * BM * 64)            // 8 KB
#define TILE_WL  (2 * BM * 64 + BN * 64)  // 8 KB
#define STAGE_BYTES  (2 * BM * 64 + 2 * BN * 64)     // 32 KB
#define SMEM_TOTAL   (STAGES * STAGE_BYTES)          // 64 KB

// SW64 swizzle for 64-byte rows: bits[4:5] ^= bits[7:8] (validated in R12)
#define SMEM_SWIZZLE_64B(off) ((off) ^ (((off) >> 3) & 0x30))

// ---------------------------------------------------------------------------
// Device scratch (allocation-free rule: __device__ globals)
// ---------------------------------------------------------------------------
__device__ float          g_coef[BATCH * 4];
__device__ __nv_bfloat16  g_Ah[BATCH * KBIG];         // 32 MB
__device__ __nv_bfloat16  g_Al[BATCH * KBIG];         // 32 MB
__device__ __nv_bfloat16  g_Wh[4 * OUT_DIM * IN_DIM]; // 8 MB
__device__ __nv_bfloat16  g_Wl[4 * OUT_DIM * IN_DIM]; // 8 MB
__device__ float          g_scratch[BATCH * OUT_DIM]; // 16 MB helper partials
__device__ int            g_flag[NTILES];

// ---------------------------------------------------------------------------
// PTX helpers (baseline ISA only)
// ---------------------------------------------------------------------------
__device__ __forceinline__ uint32_t smem_to_u32(const void* p) {
    uint32_t a;
    asm("{ .reg .u64 t; cvta.to.shared.u64 t, %1; cvt.u32.u64 %0, t; }"
        : "=r"(a) : "l"(p));
    return a;
}

__device__ __forceinline__ void cp_async16(uint32_t saddr, const void* gaddr) {
    asm volatile("cp.async.cg.shared.global [%0], [%1], 16;"
                 :: "r"(saddr), "l"(gaddr));
}

#define CP_ASYNC_COMMIT() asm volatile("cp.async.commit_group;" ::: "memory")
#define CP_ASYNC_WAIT1()  asm volatile("cp.async.wait_group 1;" ::: "memory")
#define CP_ASYNC_WAIT0()  asm volatile("cp.async.wait_group 0;" ::: "memory")

__device__ __forceinline__ void ldsm_x4(uint32_t (&r)[4], uint32_t addr) {
    asm volatile("ldmatrix.sync.aligned.m8n8.x4.shared.b16 {%0,%1,%2,%3}, [%4];"
                 : "=r"(r[0]), "=r"(r[1]), "=r"(r[2]), "=r"(r[3]) : "r"(addr));
}

__device__ __forceinline__ void mma_16816(float (&d)[4], const uint32_t (&a)[4],
                                          uint32_t b0, uint32_t b1) {
    asm volatile(
        "mma.sync.aligned.m16n8k16.row.col.f32.bf16.bf16.f32 "
        "{%0,%1,%2,%3}, {%4,%5,%6,%7}, {%8,%9}, {%0,%1,%2,%3};"
        : "+f"(d[0]), "+f"(d[1]), "+f"(d[2]), "+f"(d[3])
        : "r"(a[0]), "r"(a[1]), "r"(a[2]), "r"(a[3]), "r"(b0), "r"(b1));
}

// ---------------------------------------------------------------------------
// Split helpers
// ---------------------------------------------------------------------------
__device__ __forceinline__ uint32_t pack2bf16(__nv_bfloat16 lo, __nv_bfloat16 hi)
{
    return ((uint32_t)__bfloat16_as_ushort(hi) << 16) |
           (uint32_t)__bfloat16_as_ushort(lo);
}

__device__ __forceinline__ void split1(float a, __nv_bfloat16& h, __nv_bfloat16& l)
{
    h = __float2bfloat16(a);
    l = __float2bfloat16(a - __bfloat162float(h));
}

// ---------------------------------------------------------------------------
// Kernel 1 (merged preprocessing):
//   blocks [0, BATCH):             coef + A = c*x split into bf16 hi/lo
//   blocks [BATCH, BATCH+1024):    weights -> bf16 hi/lo (1024*256*4 = 2^20 float4)
// ---------------------------------------------------------------------------
__global__ void __launch_bounds__(256)
prep_kernel(const float* __restrict__ x,
            const float* __restrict__ phase,
            const float* __restrict__ basis,
            const float* __restrict__ w)
{
    const int iv = threadIdx.x;

    if (blockIdx.x >= BATCH) {
        const int blk = blockIdx.x - BATCH;          // 0..1023
        if (blk == 0) g_flag[iv] = 0;                // NTILES==256 flags
        size_t t0 = (size_t)blk * 1024 + iv;         // float4 index
#pragma unroll
        for (int r = 0; r < 4; r++) {
            size_t t = t0 + (size_t)r * 256;
            float4 wv = reinterpret_cast<const float4*>(w)[t];
            __nv_bfloat16 h0, h1, h2, h3, l0, l1, l2, l3;
            split1(wv.x, h0, l0); split1(wv.y, h1, l1);
            split1(wv.z, h2, l2); split1(wv.w, h3, l3);
            size_t base = t * 4;
            uint2 vh = make_uint2(pack2bf16(h0, h1), pack2bf16(h2, h3));
            uint2 vl = make_uint2(pack2bf16(l0, l1), pack2bf16(l2, l3));
            *reinterpret_cast<uint2*>(g_Wh + base) = vh;
            *reinterpret_cast<uint2*>(g_Wl + base) = vl;
        }
        return;
    }

    // ---- A split: one block per batch row ----
    const int b = blockIdx.x;
    const float HALF_PI = 1.5707963267948966f;
    float r = phase[b] / HALF_PI;
    int q = (int)floorf(r);
    q = min(max(q, 0), 3);
    float t  = r - (float)q;
    float t2 = t * t;
    float t3 = t2 * t;
    float co[4];
#pragma unroll
    for (int k = 0; k < 4; k++)
        co[k] = t3 * basis[k] + t2 * basis[4 + k] + t * basis[8 + k] + basis[12 + k];
    float cs[4];
#pragma unroll
    for (int j = 0; j < 4; j++) cs[j] = co[(j - q + 1) & 3];
    if (iv < 4) g_coef[b * 4 + iv] = cs[iv];

    float4 xv = reinterpret_cast<const float4*>(x)[b * 256 + iv];
#pragma unroll
    for (int j = 0; j < 4; j++) {
        float a0 = cs[j] * xv.x, a1 = cs[j] * xv.y;
        float a2 = cs[j] * xv.z, a3 = cs[j] * xv.w;
        __nv_bfloat16 h0, h1, h2, h3, l0, l1, l2, l3;
        split1(a0, h0, l0); split1(a1, h1, l1);
        split1(a2, h2, l2); split1(a3, h3, l3);
        size_t base = (size_t)b * KBIG + j * IN_DIM + iv * 4;
        uint2 vh = make_uint2(pack2bf16(h0, h1), pack2bf16(h2, h3));
        uint2 vl = make_uint2(pack2bf16(l0, l1), pack2bf16(l2, l3));
        *reinterpret_cast<uint2*>(g_Ah + base) = vh;
        *reinterpret_cast<uint2*>(g_Al + base) = vl;
    }
}

// ---------------------------------------------------------------------------
// Kernel 2: fused-3-segment mma.sync bf16 GEMM, 2 CTAs/SM, K-split helpers
// ---------------------------------------------------------------------------
__device__ __forceinline__ void issue_tile_load(
    uint32_t smem_base, int stage, int ck, int tid, int mBase, int nBase)
{
    const int kA = ck * BK;
    const int j  = kA >> 10;
    const int i0 = kA & (IN_DIM - 1);
    const size_t wOff = (size_t)j * (OUT_DIM * IN_DIM) + i0;

    const uint32_t st = smem_base + stage * STAGE_BYTES;

    // A planes: 128 rows x 4 vec16 = 512 vectors -> 2 iters x 2 planes
#pragma unroll
    for (int it = 0; it < 2; it++) {
        int idx = tid + it * NTHREADS;
        int row = idx >> 2;
        int cv  = idx & 3;
        size_t goff = (size_t)(mBase + row) * KBIG + kA + cv * 8;
        uint32_t soff = SMEM_SWIZZLE_64B(row * 64 + cv * 16);
        cp_async16(st + TILE_AH + soff, g_Ah + goff);
        cp_async16(st + TILE_AL + soff, g_Al + goff);
    }
    // W planes: 128 rows x 4 vec16 = 512 vectors -> 2 iters x 2 planes
#pragma unroll
    for (int it = 0; it < 2; it++) {
        int idx = tid + it * NTHREADS;
        int row = idx >> 2;
        int cv  = idx & 3;
        size_t goff = wOff + (size_t)(nBase + row) * IN_DIM + cv * 8;
        uint32_t soff = SMEM_SWIZZLE_64B(row * 64 + cv * 16);
        cp_async16(st + TILE_WH + soff, g_Wh + goff);
        cp_async16(st + TILE_WL + soff, g_Wl + goff);
    }
}

// Run nck chunks [ck0, ck0+nck), R10-style 2-stage schedule.
__device__ __forceinline__ void run_chunks(
    uint32_t smem_base, int tid, int lane, int wm, int wn,
    int mBase, int nBase, int ck0, int nck, float (&acc)[4][4][4])
{
    const int a_row  = lane & 15;
    const int a_colh = (lane >> 4) * 16;
    const int b_row  = (lane & 7) + ((lane >> 4) << 3);
    const int b_colh = ((lane >> 3) & 1) * 16;

    const int aBase = (wm * 64 + a_row) * 64 + a_colh;   // + mt*1024 + kc
    const int bBase = (wn * 32 + b_row) * 64 + b_colh;   // + nt2*1024 + kc

    issue_tile_load(smem_base, 0, ck0, tid, mBase, nBase);
    CP_ASYNC_COMMIT();
    issue_tile_load(smem_base, 1, ck0 + 1, tid, mBase, nBase);
    CP_ASYNC_COMMIT();

#pragma unroll 1
    for (int i = 0; i < nck; i++) {
        CP_ASYNC_WAIT1();
        __syncthreads();

        const uint32_t st = smem_base + (i & 1) * STAGE_BYTES;
        const uint32_t sah = st + TILE_AH;
        const uint32_t sal = st + TILE_AL;
        const uint32_t swh = st + TILE_WH;
        const uint32_t swl = st + TILE_WL;

#pragma unroll
        for (int ks = 0; ks < 2; ks++) {       // 2 x k16 within BK=32
            const int kc = ks * 32;
            uint32_t aF[4][4];     // aH, reused for aL
            uint32_t bH[4][2];
            uint32_t bX[4][2];     // bL

            // step 1: aH, bH -> aH*bH
#pragma unroll
            for (int mt = 0; mt < 4; mt++)
                ldsm_x4(aF[mt], sah + SMEM_SWIZZLE_64B(aBase + mt * 1024 + kc));
            {
                uint32_t b4[4];
                ldsm_x4(b4, swh + SMEM_SWIZZLE_64B(bBase + kc));
                bH[0][0] = b4[0]; bH[0][1] = b4[1];
                bH[1][0] = b4[2]; bH[1][1] = b4[3];
                ldsm_x4(b4, swh + SMEM_SWIZZLE_64B(bBase + 1024 + kc));
                bH[2][0] = b4[0]; bH[2][1] = b4[1];
                bH[3][0] = b4[2]; bH[3][1] = b4[3];
            }
#pragma unroll
            for (int mt = 0; mt < 4; mt++)
#pragma unroll
                for (int nt = 0; nt < 4; nt++)
                    mma_16816(acc[mt][nt], aF[mt], bH[nt][0], bH[nt][1]);

            // step 2: bL -> aH*bL
            {
                uint32_t b4[4];
                ldsm_x4(b4, swl + SMEM_SWIZZLE_64B(bBase + kc));
                bX[0][0] = b4[0]; bX[0][1] = b4[1];
                bX[1][0] = b4[2]; bX[1][1] = b4[3];
                ldsm_x4(b4, swl + SMEM_SWIZZLE_64B(bBase + 1024 + kc));
                bX[2][0] = b4[0]; bX[2][1] = b4[1];
                bX[3][0] = b4[2]; bX[3][1] = b4[3];
            }
#pragma unroll
            for (int mt = 0; mt < 4; mt++)
#pragma unroll
                for (int nt = 0; nt < 4; nt++)
                    mma_16816(acc[mt][nt], aF[mt], bX[nt][0], bX[nt][1]);

            // step 3: aL (reuses aF) -> aL*bH
#pragma unroll
            for (int mt = 0; mt < 4; mt++)
                ldsm_x4(aF[mt], sal + SMEM_SWIZZLE_64B(aBase + mt * 1024 + kc));
#pragma unroll
            for (int mt = 0; mt < 4; mt++)
#pragma unroll
                for (int nt = 0; nt < 4; nt++)
                    mma_16816(acc[mt][nt], aF[mt], bH[nt][0], bH[nt][1]);
        }

        __syncthreads();
        {
            int lck = i + STAGES;
            if (lck < nck)
                issue_tile_load(smem_base, i & 1, ck0 + lck, tid, mBase, nBase);
            CP_ASYNC_COMMIT();
        }
    }
    CP_ASYNC_WAIT0();
}

__global__ void __launch_bounds__(NTHREADS, 2)
gemm_kernel(const float* __restrict__ biases, float* __restrict__ out)
{
    extern __shared__ char smem[];
    const uint32_t smem_base = smem_to_u32(smem);
    const int tid  = threadIdx.x;
    const int wid  = tid >> 5;
    const int lane = tid & 31;
    const int wm   = wid & 1;    // 2 warp rows (64 rows each)
    const int wn   = wid >> 1;   // 4 warp cols (32 cols each)
    const int tg   = lane >> 2;
    const int tc   = (lane & 3) * 2;

    float acc[4][4][4];
#pragma unroll
    for (int i = 0; i < 4; i++)
#pragma unroll
        for (int j = 0; j < 4; j++)
#pragma unroll
            for (int k = 0; k < 4; k++) acc[i][j][k] = 0.f;

    if (blockIdx.x < NHELP) {
        // ------------- HELPER CTA: chunks [CK_MAIN, 128) for 5-6 tiles -------------
        const int h = blockIdx.x;
#pragma unroll 1
        for (int t = h; t < NTILES; t += NHELP) {
            const int mBase = (t & 31) * BM;
            const int nBase = (t >> 5) * BN;

#pragma unroll
            for (int i = 0; i < 4; i++)
#pragma unroll
                for (int j = 0; j < 4; j++)
#pragma unroll
                    for (int k = 0; k < 4; k++) acc[i][j][k] = 0.f;

            run_chunks(smem_base, tid, lane, wm, wn, mBase, nBase,
                       CK_MAIN, NCHUNK - CK_MAIN, acc);

#pragma unroll
            for (int nt = 0; nt < 4; nt++) {
                int col = nBase + wn * 32 + nt * 8 + tc;
#pragma unroll
                for (int mt = 0; mt < 4; mt++) {
                    int r0 = mBase + wm * 64 + mt * 16 + tg;
                    float2 r01 = make_float2(acc[mt][nt][0], acc[mt][nt][1]);
                    float2 r23 = make_float2(acc[mt][nt][2], acc[mt][nt][3]);
                    *reinterpret_cast<float2*>(g_scratch + (size_t)r0 * OUT_DIM + col) = r01;
                    *reinterpret_cast<float2*>(g_scratch + (size_t)(r0 + 8) * OUT_DIM + col) = r23;
                }
            }
            __threadfence();
            __syncthreads();
            if (tid == 0) {
                asm volatile("st.release.gpu.global.b32 [%0], %1;"
                             :: "l"(&g_flag[t]), "r"(1) : "memory");
            }
            __syncthreads();
        }
        return;
    }

    // --------------------- MAIN CTA: chunks [0, CK_MAIN) ---------------------
    const int t = blockIdx.x - NHELP;
    const int mBase = (t & 31) * BM;
    const int nBase = (t >> 5) * BN;

    run_chunks(smem_base, tid, lane, wm, wn, mBase, nBase, 0, CK_MAIN, acc);

    // Wait for helper partial (helpers finish earlier by construction)
    if (tid == 0) {
        int f;
        do {
            asm volatile("ld.acquire.gpu.global.b32 %0, [%1];"
                         : "=r"(f) : "l"(&g_flag[t]) : "memory");
            if (!f) __nanosleep(64);
        } while (!f);
    }
    __syncthreads();

    // ---- Epilogue: D += scratch + sum_j c_j[b] * bias_j[o] ----
    float cA[4][4], cB[4][4];
#pragma unroll
    for (int mt = 0; mt < 4; mt++) {
        int r0 = mBase + wm * 64 + mt * 16 + tg;
#pragma unroll
        for (int j = 0; j < 4; j++) {
            cA[mt][j] = g_coef[r0 * 4 + j];
            cB[mt][j] = g_coef[(r0 + 8) * 4 + j];
        }
    }

#pragma unroll
    for (int nt = 0; nt < 4; nt++) {
        int col = nBase + wn * 32 + nt * 8 + tc;
        float2 bj[4];
#pragma unroll
        for (int j = 0; j < 4; j++)
            bj[j] = *reinterpret_cast<const float2*>(biases + j * OUT_DIM + col);
#pragma unroll
        for (int mt = 0; mt < 4; mt++) {
            int r0 = mBase + wm * 64 + mt * 16 + tg;
            float2 s01 = *reinterpret_cast<const float2*>(g_scratch + (size_t)r0 * OUT_DIM + col);
            float2 s23 = *reinterpret_cast<const float2*>(g_scratch + (size_t)(r0 + 8) * OUT_DIM + col);
            float be0 = 0.f, be1 = 0.f, be2 = 0.f, be3 = 0.f;
#pragma unroll
            for (int j = 0; j < 4; j++) {
                be0 += cA[mt][j] * bj[j].x;
                be1 += cA[mt][j] * bj[j].y;
                be2 += cB[mt][j] * bj[j].x;
                be3 += cB[mt][j] * bj[j].y;
            }
            float2 r01 = make_float2(acc[mt][nt][0] + be0 + s01.x,
                                     acc[mt][nt][1] + be1 + s01.y);
            float2 r23 = make_float2(acc[mt][nt][2] + be2 + s23.x,
                                     acc[mt][nt][3] + be3 + s23.y);
            *reinterpret_cast<float2*>(out + (size_t)r0 * OUT_DIM + col) = r01;
            *reinterpret_cast<float2*>(out + (size_t)(r0 + 8) * OUT_DIM + col) = r23;
        }
    }
}

// ---------------------------------------------------------------------------
// kernel_launch
// ---------------------------------------------------------------------------
extern "C" void kernel_launch(void* const* d_in, const int* in_sizes, int n_in,
                              void* d_out, int out_size)
{
    const float* x      = (const float*)d_in[0];
    const float* phase  = (const float*)d_in[1];
    const float* w      = (const float*)d_in[2];
    const float* biases = (const float*)d_in[3];
    const float* basis  = (const float*)d_in[4];
    float* out = (float*)d_out;

    static bool attr_set = false;
    if (!attr_set) {
        cudaFuncSetAttribute(gemm_kernel,
                             cudaFuncAttributeMaxDynamicSharedMemorySize,
                             SMEM_TOTAL);
        attr_set = true;
    }

    prep_kernel<<<BATCH + 1024, 256>>>(x, phase, basis, w);
    gemm_kernel<<<NBLOCKS, NTHREADS, SMEM_TOTAL>>>(biases, out);
}

// round 14
// speedup vs baseline: 1.1152x; 1.0951x over previous
#include <cuda_runtime.h>
#include <cuda_bf16.h>
#include <cstdint>

// ---------------------------------------------------------------------------
// Problem dims
// ---------------------------------------------------------------------------
#define BATCH   4096
#define IN_DIM  1024
#define OUT_DIM 1024
#define KBIG    4096          // 4 * IN_DIM

// GEMM tiling: BM=256, BN=128, 256 threads, warp grid 4x2, warp tile 64x64
// (R10-proven shape). Fused-3-segment (Ah*Wh + Al*Wh + Ah*Wl).
// Work distribution: total work = 128 tiles x 64 chunks = 8192 chunk-units,
// flattened and split into 152 equal contiguous ranges (one per CTA). Each
// range spans at most 2 tiles; partial-tile results are atomicAdd'ed onto
// out, which prep pre-initializes with the rank-4 bias term.
#define BM 256
#define BN 128
#define BK 64                 // bf16 -> 128 bytes per row
#define NCHUNK (KBIG / BK)    // 64
#define NTILES  128           // (4096/256) * (1024/128)
#define NBLOCKS 152
#define TOTAL_UNITS (NTILES * NCHUNK)   // 8192
#define STAGES 2
#define NTHREADS 256
#define TILE_AH  0                         // 32 KB
#define TILE_AL  (BM * 128)                // 32 KB
#define TILE_WH  (2 * BM * 128)            // 16 KB
#define TILE_WL  (2 * BM * 128 + BN * 128) // 16 KB
#define STAGE_BYTES  (2 * BM * 128 + 2 * BN * 128)   // 96 KB
#define SMEM_TOTAL   (STAGES * STAGE_BYTES)          // 192 KB

#define SMEM_SWIZZLE_128B(off) ((off) ^ (((off) >> 3) & 0x70))

// ---------------------------------------------------------------------------
// Device scratch (allocation-free rule: __device__ globals)
// ---------------------------------------------------------------------------
__device__ float          g_coef[BATCH * 4];
__device__ __nv_bfloat16  g_Ah[BATCH * KBIG];         // 32 MB
__device__ __nv_bfloat16  g_Al[BATCH * KBIG];         // 32 MB
__device__ __nv_bfloat16  g_Wh[4 * OUT_DIM * IN_DIM]; // 8 MB
__device__ __nv_bfloat16  g_Wl[4 * OUT_DIM * IN_DIM]; // 8 MB

// ---------------------------------------------------------------------------
// PTX helpers (baseline ISA only)
// ---------------------------------------------------------------------------
__device__ __forceinline__ uint32_t smem_to_u32(const void* p) {
    uint32_t a;
    asm("{ .reg .u64 t; cvta.to.shared.u64 t, %1; cvt.u32.u64 %0, t; }"
        : "=r"(a) : "l"(p));
    return a;
}

__device__ __forceinline__ void cp_async16(uint32_t saddr, const void* gaddr) {
    asm volatile("cp.async.cg.shared.global [%0], [%1], 16;"
                 :: "r"(saddr), "l"(gaddr));
}

#define CP_ASYNC_COMMIT() asm volatile("cp.async.commit_group;" ::: "memory")
#define CP_ASYNC_WAIT1()  asm volatile("cp.async.wait_group 1;" ::: "memory")
#define CP_ASYNC_WAIT0()  asm volatile("cp.async.wait_group 0;" ::: "memory")

__device__ __forceinline__ void ldsm_x4(uint32_t (&r)[4], uint32_t addr) {
    asm volatile("ldmatrix.sync.aligned.m8n8.x4.shared.b16 {%0,%1,%2,%3}, [%4];"
                 : "=r"(r[0]), "=r"(r[1]), "=r"(r[2]), "=r"(r[3]) : "r"(addr));
}

__device__ __forceinline__ void mma_16816(float (&d)[4], const uint32_t (&a)[4],
                                          uint32_t b0, uint32_t b1) {
    asm volatile(
        "mma.sync.aligned.m16n8k16.row.col.f32.bf16.bf16.f32 "
        "{%0,%1,%2,%3}, {%4,%5,%6,%7}, {%8,%9}, {%0,%1,%2,%3};"
        : "+f"(d[0]), "+f"(d[1]), "+f"(d[2]), "+f"(d[3])
        : "r"(a[0]), "r"(a[1]), "r"(a[2]), "r"(a[3]), "r"(b0), "r"(b1));
}

// ---------------------------------------------------------------------------
// Split helpers
// ---------------------------------------------------------------------------
__device__ __forceinline__ uint32_t pack2bf16(__nv_bfloat16 lo, __nv_bfloat16 hi)
{
    return ((uint32_t)__bfloat16_as_ushort(hi) << 16) |
           (uint32_t)__bfloat16_as_ushort(lo);
}

__device__ __forceinline__ void split1(float a, __nv_bfloat16& h, __nv_bfloat16& l)
{
    h = __float2bfloat16(a);
    l = __float2bfloat16(a - __bfloat162float(h));
}

// ---------------------------------------------------------------------------
// Kernel 1 (merged preprocessing):
//   blocks [0, BATCH):             coef + A split + out = rank-4 bias init
//   blocks [BATCH, BATCH+1024):    weights -> bf16 hi/lo
// ---------------------------------------------------------------------------
__global__ void __launch_bounds__(256)
prep_kernel(const float* __restrict__ x,
            const float* __restrict__ phase,
            const float* __restrict__ basis,
            const float* __restrict__ w,
            const float* __restrict__ biases,
            float* __restrict__ out)
{
    const int iv = threadIdx.x;

    if (blockIdx.x >= BATCH) {
        const int blk = blockIdx.x - BATCH;          // 0..1023
        size_t t0 = (size_t)blk * 1024 + iv;         // float4 index
#pragma unroll
        for (int r = 0; r < 4; r++) {
            size_t t = t0 + (size_t)r * 256;
            float4 wv = reinterpret_cast<const float4*>(w)[t];
            __nv_bfloat16 h0, h1, h2, h3, l0, l1, l2, l3;
            split1(wv.x, h0, l0); split1(wv.y, h1, l1);
            split1(wv.z, h2, l2); split1(wv.w, h3, l3);
            size_t base = t * 4;
            uint2 vh = make_uint2(pack2bf16(h0, h1), pack2bf16(h2, h3));
            uint2 vl = make_uint2(pack2bf16(l0, l1), pack2bf16(l2, l3));
            *reinterpret_cast<uint2*>(g_Wh + base) = vh;
            *reinterpret_cast<uint2*>(g_Wl + base) = vl;
        }
        return;
    }

    // ---- A split + bias init: one block per batch row ----
    const int b = blockIdx.x;
    const float HALF_PI = 1.5707963267948966f;
    float r = phase[b] / HALF_PI;
    int q = (int)floorf(r);
    q = min(max(q, 0), 3);
    float t  = r - (float)q;
    float t2 = t * t;
    float t3 = t2 * t;
    float co[4];
#pragma unroll
    for (int k = 0; k < 4; k++)
        co[k] = t3 * basis[k] + t2 * basis[4 + k] + t * basis[8 + k] + basis[12 + k];
    float cs[4];
#pragma unroll
    for (int j = 0; j < 4; j++) cs[j] = co[(j - q + 1) & 3];
    if (iv < 4) g_coef[b * 4 + iv] = cs[iv];

    float4 xv = reinterpret_cast<const float4*>(x)[b * 256 + iv];
#pragma unroll
    for (int j = 0; j < 4; j++) {
        float a0 = cs[j] * xv.x, a1 = cs[j] * xv.y;
        float a2 = cs[j] * xv.z, a3 = cs[j] * xv.w;
        __nv_bfloat16 h0, h1, h2, h3, l0, l1, l2, l3;
        split1(a0, h0, l0); split1(a1, h1, l1);
        split1(a2, h2, l2); split1(a3, h3, l3);
        size_t base = (size_t)b * KBIG + j * IN_DIM + iv * 4;
        uint2 vh = make_uint2(pack2bf16(h0, h1), pack2bf16(h2, h3));
        uint2 vl = make_uint2(pack2bf16(l0, l1), pack2bf16(l2, l3));
        *reinterpret_cast<uint2*>(g_Ah + base) = vh;
        *reinterpret_cast<uint2*>(g_Al + base) = vl;
    }

    // out[b, :] = sum_j cs[j] * biases[j][:]   (gemm atomically adds on top)
    {
        int o = iv * 4;
        float4 b0 = *reinterpret_cast<const float4*>(biases + 0 * OUT_DIM + o);
        float4 b1 = *reinterpret_cast<const float4*>(biases + 1 * OUT_DIM + o);
        float4 b2 = *reinterpret_cast<const float4*>(biases + 2 * OUT_DIM + o);
        float4 b3 = *reinterpret_cast<const float4*>(biases + 3 * OUT_DIM + o);
        float4 rr;
        rr.x = cs[0] * b0.x + cs[1] * b1.x + cs[2] * b2.x + cs[3] * b3.x;
        rr.y = cs[0] * b0.y + cs[1] * b1.y + cs[2] * b2.y + cs[3] * b3.y;
        rr.z = cs[0] * b0.z + cs[1] * b1.z + cs[2] * b2.z + cs[3] * b3.z;
        rr.w = cs[0] * b0.w + cs[1] * b1.w + cs[2] * b2.w + cs[3] * b3.w;
        *reinterpret_cast<float4*>(out + (size_t)b * OUT_DIM + o) = rr;
    }
}

// ---------------------------------------------------------------------------
// Kernel 2: fused-3-segment mma.sync bf16 GEMM, flattened 152-way work split
// ---------------------------------------------------------------------------
__device__ __forceinline__ void issue_tile_load(
    uint32_t smem_base, int stage, int ck, int tid, int mBase, int nBase)
{
    const int kA = ck * BK;
    const int j  = kA >> 10;
    const int i0 = kA & (IN_DIM - 1);
    const size_t wOff = (size_t)j * (OUT_DIM * IN_DIM) + i0;

    const uint32_t st = smem_base + stage * STAGE_BYTES;

#pragma unroll
    for (int it = 0; it < 8; it++) {
        int idx = tid + it * NTHREADS;
        int row = idx >> 3;
        int cv  = idx & 7;
        size_t goff = (size_t)(mBase + row) * KBIG + kA + cv * 8;
        uint32_t soff = SMEM_SWIZZLE_128B(row * 128 + cv * 16);
        cp_async16(st + TILE_AH + soff, g_Ah + goff);
        cp_async16(st + TILE_AL + soff, g_Al + goff);
    }
#pragma unroll
    for (int it = 0; it < 4; it++) {
        int idx = tid + it * NTHREADS;
        int row = idx >> 3;
        int cv  = idx & 7;
        size_t goff = wOff + (size_t)(nBase + row) * IN_DIM + cv * 8;
        uint32_t soff = SMEM_SWIZZLE_128B(row * 128 + cv * 16);
        cp_async16(st + TILE_WH + soff, g_Wh + goff);
        cp_async16(st + TILE_WL + soff, g_Wl + goff);
    }
}

// Run nck chunks [ck0, ck0+nck) of one tile (R10-proven schedule).
__device__ __forceinline__ void run_chunks(
    uint32_t smem_base, int tid, int lane, int wm, int wn,
    int mBase, int nBase, int ck0, int nck, float (&acc)[4][8][4])
{
    const int a_row  = lane & 15;
    const int a_colh = (lane >> 4) * 16;
    const int b_row  = (lane & 7) + ((lane >> 4) << 3);
    const int b_colh = ((lane >> 3) & 1) * 16;

    const int aBase = (wm * 64 + a_row) * 128 + a_colh;
    const int bBase = (wn * 64 + b_row) * 128 + b_colh;

    issue_tile_load(smem_base, 0, ck0, tid, mBase, nBase);
    CP_ASYNC_COMMIT();
    if (nck > 1) issue_tile_load(smem_base, 1, ck0 + 1, tid, mBase, nBase);
    CP_ASYNC_COMMIT();

#pragma unroll 1
    for (int i = 0; i < nck; i++) {
        CP_ASYNC_WAIT1();
        __syncthreads();

        const uint32_t st = smem_base + (i & 1) * STAGE_BYTES;
        const uint32_t sah = st + TILE_AH;
        const uint32_t sal = st + TILE_AL;
        const uint32_t swh = st + TILE_WH;
        const uint32_t swl = st + TILE_WL;

#pragma unroll
        for (int ks = 0; ks < 4; ks++) {
            const int kc = ks * 32;
            uint32_t aF[4][4];     // aH, reused for aL
            uint32_t bH[8][2];
            uint32_t bX[8][2];     // bL

            // step 1: aH, bH -> aH*bH
#pragma unroll
            for (int mt = 0; mt < 4; mt++)
                ldsm_x4(aF[mt], sah + SMEM_SWIZZLE_128B(aBase + mt * 2048 + kc));
#pragma unroll
            for (int nt2 = 0; nt2 < 4; nt2++) {
                uint32_t b4[4];
                ldsm_x4(b4, swh + SMEM_SWIZZLE_128B(bBase + nt2 * 2048 + kc));
                bH[nt2 * 2 + 0][0] = b4[0]; bH[nt2 * 2 + 0][1] = b4[1];
                bH[nt2 * 2 + 1][0] = b4[2]; bH[nt2 * 2 + 1][1] = b4[3];
            }
#pragma unroll
            for (int mt = 0; mt < 4; mt++)
#pragma unroll
                for (int nt = 0; nt < 8; nt++)
                    mma_16816(acc[mt][nt], aF[mt], bH[nt][0], bH[nt][1]);

            // step 2: bL -> aH*bL
#pragma unroll
            for (int nt2 = 0; nt2 < 4; nt2++) {
                uint32_t b4[4];
                ldsm_x4(b4, swl + SMEM_SWIZZLE_128B(bBase + nt2 * 2048 + kc));
                bX[nt2 * 2 + 0][0] = b4[0]; bX[nt2 * 2 + 0][1] = b4[1];
                bX[nt2 * 2 + 1][0] = b4[2]; bX[nt2 * 2 + 1][1] = b4[3];
            }
#pragma unroll
            for (int mt = 0; mt < 4; mt++)
#pragma unroll
                for (int nt = 0; nt < 8; nt++)
                    mma_16816(acc[mt][nt], aF[mt], bX[nt][0], bX[nt][1]);

            // step 3: aL (reuses aF) -> aL*bH
#pragma unroll
            for (int mt = 0; mt < 4; mt++)
                ldsm_x4(aF[mt], sal + SMEM_SWIZZLE_128B(aBase + mt * 2048 + kc));
#pragma unroll
            for (int mt = 0; mt < 4; mt++)
#pragma unroll
                for (int nt = 0; nt < 8; nt++)
                    mma_16816(acc[mt][nt], aF[mt], bH[nt][0], bH[nt][1]);
        }

        __syncthreads();
        {
            int lck = i + STAGES;
            if (lck < nck)
                issue_tile_load(smem_base, i & 1, ck0 + lck, tid, mBase, nBase);
            CP_ASYNC_COMMIT();
        }
    }
    CP_ASYNC_WAIT0();
}

__global__ void __launch_bounds__(NTHREADS, 1)
gemm_kernel(float* __restrict__ out)
{
    extern __shared__ char smem[];
    const uint32_t smem_base = smem_to_u32(smem);
    const int tid  = threadIdx.x;
    const int wid  = tid >> 5;
    const int lane = tid & 31;
    const int wm   = wid & 3;    // 4 warp rows (64 rows each)
    const int wn   = wid >> 2;   // 2 warp cols (64 cols each)
    const int tg   = lane >> 2;
    const int tc   = (lane & 3) * 2;

    const int r = blockIdx.x;
    int u0 = (r * TOTAL_UNITS) / NBLOCKS;
    const int u1 = ((r + 1) * TOTAL_UNITS) / NBLOCKS;

#pragma unroll 1
    while (u0 < u1) {
        const int t     = u0 >> 6;                 // tile index
        const int c0    = u0 & 63;                 // first chunk in tile
        const int cend  = min(u1 - (t << 6), 64);  // end chunk (exclusive)
        const int mBase = (t & 15) * BM;
        const int nBase = (t >> 4) * BN;

        float acc[4][8][4];
#pragma unroll
        for (int i = 0; i < 4; i++)
#pragma unroll
            for (int j = 0; j < 8; j++)
#pragma unroll
                for (int k = 0; k < 4; k++) acc[i][j][k] = 0.f;

        run_chunks(smem_base, tid, lane, wm, wn, mBase, nBase,
                   c0, cend - c0, acc);

        // Atomic-add epilogue (out pre-initialized with bias by prep)
#pragma unroll
        for (int nt = 0; nt < 8; nt++) {
            int col = nBase + wn * 64 + nt * 8 + tc;
#pragma unroll
            for (int mt = 0; mt < 4; mt++) {
                int r0 = mBase + wm * 64 + mt * 16 + tg;
                float* p0 = out + (size_t)r0 * OUT_DIM + col;
                float* p1 = out + (size_t)(r0 + 8) * OUT_DIM + col;
                atomicAdd(p0,     acc[mt][nt][0]);
                atomicAdd(p0 + 1, acc[mt][nt][1]);
                atomicAdd(p1,     acc[mt][nt][2]);
                atomicAdd(p1 + 1, acc[mt][nt][3]);
            }
        }
        __syncthreads();   // all warps done before next segment reuses smem
        u0 = (t << 6) + cend;
    }
}

// ---------------------------------------------------------------------------
// kernel_launch
// ---------------------------------------------------------------------------
extern "C" void kernel_launch(void* const* d_in, const int* in_sizes, int n_in,
                              void* d_out, int out_size)
{
    const float* x      = (const float*)d_in[0];
    const float* phase  = (const float*)d_in[1];
    const float* w      = (const float*)d_in[2];
    const float* biases = (const float*)d_in[3];
    const float* basis  = (const float*)d_in[4];
    float* out = (float*)d_out;

    static bool attr_set = false;
    if (!attr_set) {
        cudaFuncSetAttribute(gemm_kernel,
                             cudaFuncAttributeMaxDynamicSharedMemorySize,
                             SMEM_TOTAL);
        attr_set = true;
    }

    prep_kernel<<<BATCH + 1024, 256>>>(x, phase, basis, w, biases, out);
    gemm_kernel<<<NBLOCKS, NTHREADS, SMEM_TOTAL>>>(out);
}